// round 12
// baseline (speedup 1.0000x reference)
#include <cuda_runtime.h>
#include <cuda_bf16.h>
#include <math.h>
#include <mma.h>

using namespace nvcuda;

#define N_NODES  10000
#define M_PAD    10112          // 158 * 64
#define N_EDGES  320000
#define N_GRAPHS 64
#define D1 128
#define D2 256
#define CAP 128                 // per-node slot capacity (Poisson(32), max ~57)

// ---------------- scratch (zero-initialized at load; self-cleaning per call) ----------------
__device__ int            g_cnt[N_NODES];            // reset by k_mlp each call
__device__ int            g_slot[N_NODES * CAP];
__device__ float          g_A1[N_NODES * D1];
__device__ __nv_bfloat16  g_B1h[N_NODES * D1];       // bf16 gather table, layer 1
__device__ __nv_bfloat16  g_h1[M_PAD * D1];          // pad rows stay 0 forever
__device__ __nv_bfloat16  g_Wcat[128 * 512];         // bf16 [k][n]: n<256 -> W2a-W2b else W2b
__device__ float          g_C2A[M_PAD * 256];        // fp32 A2 (self term)
__device__ __nv_bfloat16  g_B2h[M_PAD * 256];        // bf16 gather table, layer 2
__device__ float          g_pool[N_GRAPHS * D2];     // reset by k_mlp each call

__device__ __forceinline__ float sigmoidf(float x) {
    return 1.0f / (1.0f + __expf(-x));
}
__device__ __forceinline__ __nv_bfloat162 bmax(__nv_bfloat162 a, unsigned int b) {
    return __hmax2(a, *(__nv_bfloat162*)&b);
}

// ---------------- kernel 0: prep = gemm1 + wcat + edge scatter (fused) ----------------
__global__ __launch_bounds__(256) void k_prep(const float* __restrict__ x,
                                              const float* __restrict__ W1,
                                              const float* __restrict__ W2,
                                              const int* __restrict__ ei) {
    int i = blockIdx.x * blockDim.x + threadIdx.x;
    int stride = gridDim.x * blockDim.x;
    for (int idx = i; idx < N_NODES * D1; idx += stride) {
        int n = idx >> 7;
        int d = idx & 127;
        float x0 = x[n * 3 + 0], x1 = x[n * 3 + 1], x2 = x[n * 3 + 2];
        float wb0 = W1[3 * D1 + d], wb1 = W1[4 * D1 + d], wb2 = W1[5 * D1 + d];
        float wa0 = W1[0 * D1 + d], wa1 = W1[1 * D1 + d], wa2 = W1[2 * D1 + d];
        g_B1h[idx] = __float2bfloat16(x0 * wb0 + x1 * wb1 + x2 * wb2);
        g_A1[idx]  = x0 * (wa0 - wb0) + x1 * (wa1 - wb1) + x2 * (wa2 - wb2);
    }
    for (int idx = i; idx < 128 * 512; idx += stride) {
        int k = idx >> 9;
        int n = idx & 511;
        float v;
        if (n < 256) v = W2[k * 256 + n] - W2[(128 + k) * 256 + n];
        else         v = W2[(128 + k) * 256 + (n - 256)];
        g_Wcat[idx] = __float2bfloat16(v);
    }
    for (int t = i; t < N_EDGES / 2; t += stride) {
        int e = t * 2;
        int2 s = *(const int2*)&ei[e];
        int2 d = *(const int2*)&ei[N_EDGES + e];
        int p0 = atomicAdd(&g_cnt[d.x], 1);
        g_slot[d.x * CAP + p0] = s.x;
        int p1 = atomicAdd(&g_cnt[d.y], 1);
        g_slot[d.y * CAP + p1] = s.y;
    }
}

// ---------------- kernel 1: aggregate layer 1 -> h1 bf16 (warp/node, unroll 16) ----------------
__global__ __launch_bounds__(256) void k_agg1(const float* __restrict__ b1) {
    int gw = (blockIdx.x * blockDim.x + threadIdx.x) >> 5;
    if (gw >= N_NODES) return;
    int lane = threadIdx.x & 31;
    int cnt = g_cnt[gw];
    const int* slots = &g_slot[gw * CAP];
    const int off = lane * 4;

    __nv_bfloat162 ninf = __floats2bfloat162_rn(-INFINITY, -INFINITY);
    __nv_bfloat162 m0 = ninf, m1 = ninf;
    int j = 0;
    for (; j + 16 <= cnt; j += 16) {
        uint2 v[16];
        #pragma unroll
        for (int q = 0; q < 4; q++) {
            int4 sv = *(const int4*)&slots[j + q * 4];
            v[q * 4 + 0] = *(const uint2*)&g_B1h[sv.x * D1 + off];
            v[q * 4 + 1] = *(const uint2*)&g_B1h[sv.y * D1 + off];
            v[q * 4 + 2] = *(const uint2*)&g_B1h[sv.z * D1 + off];
            v[q * 4 + 3] = *(const uint2*)&g_B1h[sv.w * D1 + off];
        }
        #pragma unroll
        for (int u = 0; u < 16; u++) { m0 = bmax(m0, v[u].x); m1 = bmax(m1, v[u].y); }
    }
    for (; j + 4 <= cnt; j += 4) {
        int4 sv = *(const int4*)&slots[j];
        uint2 v0 = *(const uint2*)&g_B1h[sv.x * D1 + off];
        uint2 v1 = *(const uint2*)&g_B1h[sv.y * D1 + off];
        uint2 v2 = *(const uint2*)&g_B1h[sv.z * D1 + off];
        uint2 v3 = *(const uint2*)&g_B1h[sv.w * D1 + off];
        m0 = bmax(bmax(bmax(bmax(m0, v0.x), v1.x), v2.x), v3.x);
        m1 = bmax(bmax(bmax(bmax(m1, v0.y), v1.y), v2.y), v3.y);
    }
    for (; j < cnt; j++) {
        int s = slots[j];
        uint2 v = *(const uint2*)&g_B1h[s * D1 + off];
        m0 = bmax(m0, v.x);
        m1 = bmax(m1, v.y);
    }
    float h0 = 0.f, h1v = 0.f, h2 = 0.f, h3 = 0.f;
    if (cnt > 0) {
        float4 a  = *(const float4*)&g_A1[gw * D1 + off];
        float4 bb = *(const float4*)&b1[off];
        h0  = sigmoidf(a.x + bb.x + __bfloat162float(__low2bfloat16(m0)));
        h1v = sigmoidf(a.y + bb.y + __bfloat162float(__high2bfloat16(m0)));
        h2  = sigmoidf(a.z + bb.z + __bfloat162float(__low2bfloat16(m1)));
        h3  = sigmoidf(a.w + bb.w + __bfloat162float(__high2bfloat16(m1)));
    }
    __nv_bfloat162 o0 = __floats2bfloat162_rn(h0, h1v);
    __nv_bfloat162 o1 = __floats2bfloat162_rn(h2, h3);
    uint2 o;
    o.x = *(unsigned int*)&o0;
    o.y = *(unsigned int*)&o1;
    *(uint2*)&g_h1[gw * D1 + off] = o;
}

// ---------------- kernel 2: GEMM2 bf16 WMMA, 64x(64+64) block, paired n-tiles, BK=64 ------
__global__ __launch_bounds__(128) void k_gemm2() {
    __shared__ __nv_bfloat16 As[64 * 72];      // [m][k-chunk] pad 72
    __shared__ __nv_bfloat16 Bs0[64 * 72];     // [k][n] A-half cols
    __shared__ __nv_bfloat16 Bs1[64 * 72];     // [k][n] B-half cols
    const int tid = threadIdx.x;               // 0..127
    const int bm = blockIdx.x * 64;
    const int n0 = blockIdx.y * 64;            // 0..192
    const int warp = tid >> 5;
    const int lane = tid & 31;
    const int wm = (warp & 1) * 32;
    const int wn = (warp >> 1) * 32;

    wmma::fragment<wmma::accumulator, 16, 16, 16, float> acc0[2][2], acc1[2][2];
    #pragma unroll
    for (int i = 0; i < 2; i++)
        #pragma unroll
        for (int j = 0; j < 2; j++) {
            wmma::fill_fragment(acc0[i][j], 0.0f);
            wmma::fill_fragment(acc1[i][j], 0.0f);
        }

    #pragma unroll
    for (int kc = 0; kc < 128; kc += 64) {
        #pragma unroll
        for (int r = 0; r < 4; r++) {
            int f = tid + r * 128;
            int m = f >> 3;
            int q = f & 7;
            float4 v = *(const float4*)&g_h1[(bm + m) * D1 + kc + q * 8];
            *(float4*)&As[m * 72 + q * 8] = v;
        }
        #pragma unroll
        for (int r = 0; r < 4; r++) {
            int f = tid + r * 128;
            int k = f >> 3;
            int q = f & 7;
            float4 v0 = *(const float4*)&g_Wcat[(kc + k) * 512 + n0 + q * 8];
            float4 v1 = *(const float4*)&g_Wcat[(kc + k) * 512 + n0 + 256 + q * 8];
            *(float4*)&Bs0[k * 72 + q * 8] = v0;
            *(float4*)&Bs1[k * 72 + q * 8] = v1;
        }
        __syncthreads();
        #pragma unroll
        for (int kk = 0; kk < 64; kk += 16) {
            wmma::fragment<wmma::matrix_a, 16, 16, 16, __nv_bfloat16, wmma::row_major> a[2];
            wmma::fragment<wmma::matrix_b, 16, 16, 16, __nv_bfloat16, wmma::row_major> b0[2], b1[2];
            #pragma unroll
            for (int i = 0; i < 2; i++)
                wmma::load_matrix_sync(a[i], &As[(wm + i * 16) * 72 + kk], 72);
            #pragma unroll
            for (int j = 0; j < 2; j++) {
                wmma::load_matrix_sync(b0[j], &Bs0[kk * 72 + wn + j * 16], 72);
                wmma::load_matrix_sync(b1[j], &Bs1[kk * 72 + wn + j * 16], 72);
            }
            #pragma unroll
            for (int i = 0; i < 2; i++)
                #pragma unroll
                for (int j = 0; j < 2; j++) {
                    wmma::mma_sync(acc0[i][j], a[i], b0[j], acc0[i][j]);
                    wmma::mma_sync(acc1[i][j], a[i], b1[j], acc1[i][j]);
                }
        }
        __syncthreads();
    }

    #pragma unroll
    for (int i = 0; i < 2; i++)
        #pragma unroll
        for (int j = 0; j < 2; j++)
            wmma::store_matrix_sync(&g_C2A[(bm + wm + i * 16) * 256 + n0 + wn + j * 16],
                                    acc0[i][j], 256, wmma::mem_row_major);
    float* cs = (float*)As + warp * 256;
    #pragma unroll
    for (int i = 0; i < 2; i++)
        #pragma unroll
        for (int j = 0; j < 2; j++) {
            wmma::store_matrix_sync(cs, acc1[i][j], 16, wmma::mem_row_major);
            __syncwarp();
            int r = lane >> 1;
            int cb = (lane & 1) * 8;
            int mrow = bm + wm + i * 16 + r;
            int ncol = n0 + wn + j * 16 + cb;
            const float* src = &cs[r * 16 + cb];
            __nv_bfloat16* dst = &g_B2h[mrow * 256 + ncol];
            #pragma unroll
            for (int u = 0; u < 4; u++) {
                __nv_bfloat162 p = __floats2bfloat162_rn(src[u * 2], src[u * 2 + 1]);
                *(__nv_bfloat162*)&dst[u * 2] = p;
            }
            __syncwarp();
        }
}

// ---------------- kernel 3: agg2 + pool (2 warps/node, reg-resident slots + shfl) ----------
// Slot indices preloaded into 2 regs/lane (cnt <= 64); per-edge index via __shfl_sync.
// Removes the slot-load -> gather address dependency from every loop iteration.
__global__ __launch_bounds__(256) void k_agg2_pool(const float* __restrict__ b2,
                                                   const int* __restrict__ batch) {
    int gw = (blockIdx.x * blockDim.x + threadIdx.x) >> 5;
    int node = gw >> 1;
    if (node >= N_NODES) return;
    int half = gw & 1;
    int lane = threadIdx.x & 31;
    int cnt = g_cnt[node];
    if (cnt == 0) return;
    const int* slots = &g_slot[node * CAP];
    const int off = half * 128 + lane * 4;

    // preload slot indices into registers (CAP=128 so reads are in-bounds; content
    // beyond cnt is never consumed)
    int idx0 = slots[lane];
    int idx1 = slots[32 + lane];
    // hoist independent self-term loads above the gather loop
    float4 p = *(const float4*)&g_C2A[node * 256 + off];
    float4 q = *(const float4*)&b2[off];
    int b = batch[node];

    __nv_bfloat162 ninf = __floats2bfloat162_rn(-INFINITY, -INFINITY);
    __nv_bfloat162 m0 = ninf, m1 = ninf;
    int j = 0;
    for (; j + 8 <= cnt; j += 8) {
        int s[8];
        #pragma unroll
        for (int u = 0; u < 8; u++) {
            int jj = j + u;
            int vsrc = (jj < 32) ? idx0 : idx1;
            s[u] = __shfl_sync(0xffffffffu, vsrc, jj & 31);
        }
        uint2 v[8];
        #pragma unroll
        for (int u = 0; u < 8; u++)
            v[u] = *(const uint2*)&g_B2h[s[u] * 256 + off];
        #pragma unroll
        for (int u = 0; u < 8; u++) { m0 = bmax(m0, v[u].x); m1 = bmax(m1, v[u].y); }
    }
    for (; j < cnt; j++) {
        int vsrc = (j < 32) ? idx0 : idx1;
        int s = __shfl_sync(0xffffffffu, vsrc, j & 31);
        uint2 v = *(const uint2*)&g_B2h[s * 256 + off];
        m0 = bmax(m0, v.x);
        m1 = bmax(m1, v.y);
    }
    float h0 = sigmoidf(p.x + q.x + __bfloat162float(__low2bfloat16(m0)));
    float h1 = sigmoidf(p.y + q.y + __bfloat162float(__high2bfloat16(m0)));
    float h2 = sigmoidf(p.z + q.z + __bfloat162float(__low2bfloat16(m1)));
    float h3 = sigmoidf(p.w + q.w + __bfloat162float(__high2bfloat16(m1)));
    int* pool = (int*)&g_pool[b * D2 + off];
    atomicMax(&pool[0], __float_as_int(h0));
    atomicMax(&pool[1], __float_as_int(h1));
    atomicMax(&pool[2], __float_as_int(h2));
    atomicMax(&pool[3], __float_as_int(h3));
}

// ---------------- kernel 4: final MLP + state reset for next call ----------------
__global__ void k_mlp(const float* __restrict__ W3, const float* __restrict__ b3,
                      const float* __restrict__ W4, const float* __restrict__ b4,
                      float* __restrict__ out) {
    __shared__ float grow[256];
    __shared__ float tv[128];
    int b = blockIdx.x;
    int t = threadIdx.x;
    grow[t] = g_pool[b * D2 + t];
    grow[t + 128] = g_pool[b * D2 + t + 128];
    __syncthreads();
    g_pool[b * D2 + t] = 0.0f;
    g_pool[b * D2 + t + 128] = 0.0f;
    for (int i = b * 128 + t; i < N_NODES; i += N_GRAPHS * 128) g_cnt[i] = 0;

    float s = b3[t];
    #pragma unroll 8
    for (int k = 0; k < 256; k++)
        s += grow[k] * W3[k * 128 + t];
    tv[t] = sigmoidf(s);
    __syncthreads();
    if (t < 10) {
        float o = b4[t];
        #pragma unroll 8
        for (int d = 0; d < 128; d++)
            o += tv[d] * W4[d * 10 + t];
        out[b * 10 + t] = o;
    }
}

// ---------------- launch ----------------
extern "C" void kernel_launch(void* const* d_in, const int* in_sizes, int n_in,
                              void* d_out, int out_size) {
    const float* x  = (const float*)d_in[0];
    const int*   ei = (const int*)d_in[1];
    const int*   bt = (const int*)d_in[2];
    const float* W1 = (const float*)d_in[3];
    const float* b1 = (const float*)d_in[4];
    const float* W2 = (const float*)d_in[5];
    const float* b2 = (const float*)d_in[6];
    const float* W3 = (const float*)d_in[7];
    const float* b3 = (const float*)d_in[8];
    const float* W4 = (const float*)d_in[9];
    const float* b4 = (const float*)d_in[10];
    float* out = (float*)d_out;

    k_prep<<<640, 256>>>(x, W1, W2, ei);                      // launch 0
    k_agg1<<<(N_NODES * 32 + 255) / 256, 256>>>(b1);          // launch 1
    dim3 g2(M_PAD / 64, 4);
    k_gemm2<<<g2, 128>>>();                                   // launch 2
    k_agg2_pool<<<(N_NODES * 64 + 255) / 256, 256>>>(b2, bt); // launch 3 (ncu sample)
    k_mlp<<<N_GRAPHS, 128>>>(W3, b3, W4, b4, out);            // launch 4
}

// round 13
// speedup vs baseline: 1.0086x; 1.0086x over previous
#include <cuda_runtime.h>
#include <cuda_bf16.h>
#include <math.h>
#include <mma.h>

using namespace nvcuda;

#define N_NODES  10000
#define M_PAD    10112          // 158 * 64
#define N_EDGES  320000
#define N_GRAPHS 64
#define D1 128
#define D2 256
#define CAP 128                 // per-node slot capacity (Poisson(32), max ~57)

// ---------------- scratch (zero-initialized at load; self-cleaning per call) ----------------
__device__ int            g_cnt[N_NODES];            // reset by k_mlp each call
__device__ int            g_slot[N_NODES * CAP];
__device__ __nv_bfloat16  g_B1h[N_NODES * D1];       // bf16 gather table, layer 1
__device__ __nv_bfloat16  g_h1[M_PAD * D1];          // pad rows stay 0 forever
__device__ __nv_bfloat16  g_Wcat[128 * 512];         // bf16 [k][n]: n<256 -> W2a-W2b else W2b
__device__ float          g_C2A[M_PAD * 256];        // fp32 A2 (self term)
__device__ __nv_bfloat16  g_B2h[M_PAD * 256];        // bf16 gather table, layer 2
__device__ float          g_pool[N_GRAPHS * D2];     // reset by k_mlp each call

__device__ __forceinline__ float sigmoidf(float x) {
    return 1.0f / (1.0f + __expf(-x));
}
__device__ __forceinline__ __nv_bfloat162 bmax(__nv_bfloat162 a, unsigned int b) {
    return __hmax2(a, *(__nv_bfloat162*)&b);
}

// ---------------- kernel 0: prep = B1h transform + wcat + edge scatter ----------------
__global__ __launch_bounds__(256) void k_prep(const float* __restrict__ x,
                                              const float* __restrict__ W1,
                                              const float* __restrict__ W2,
                                              const int* __restrict__ ei) {
    int i = blockIdx.x * blockDim.x + threadIdx.x;
    int stride = gridDim.x * blockDim.x;
    // B1 = x @ Wb -> bf16 gather table (A1 is recomputed inline in agg1)
    for (int idx = i; idx < N_NODES * D1; idx += stride) {
        int n = idx >> 7;
        int d = idx & 127;
        float x0 = x[n * 3 + 0], x1 = x[n * 3 + 1], x2 = x[n * 3 + 2];
        float wb0 = W1[3 * D1 + d], wb1 = W1[4 * D1 + d], wb2 = W1[5 * D1 + d];
        g_B1h[idx] = __float2bfloat16(x0 * wb0 + x1 * wb1 + x2 * wb2);
    }
    // Wcat build (bf16)
    for (int idx = i; idx < 128 * 512; idx += stride) {
        int k = idx >> 9;
        int n = idx & 511;
        float v;
        if (n < 256) v = W2[k * 256 + n] - W2[(128 + k) * 256 + n];
        else         v = W2[(128 + k) * 256 + (n - 256)];
        g_Wcat[idx] = __float2bfloat16(v);
    }
    // edge scatter, 4 edges/thread via int4
    for (int t = i; t < N_EDGES / 4; t += stride) {
        int e = t * 4;
        int4 s = *(const int4*)&ei[e];
        int4 d = *(const int4*)&ei[N_EDGES + e];
        int p0 = atomicAdd(&g_cnt[d.x], 1);
        g_slot[d.x * CAP + p0] = s.x;
        int p1 = atomicAdd(&g_cnt[d.y], 1);
        g_slot[d.y * CAP + p1] = s.y;
        int p2 = atomicAdd(&g_cnt[d.z], 1);
        g_slot[d.z * CAP + p2] = s.z;
        int p3 = atomicAdd(&g_cnt[d.w], 1);
        g_slot[d.w * CAP + p3] = s.w;
    }
}

// ---------------- kernel 1: agg layer 1 -> h1 bf16 (warp/node, unroll 16, inline A1) -------
__global__ __launch_bounds__(256) void k_agg1(const float* __restrict__ b1,
                                              const float* __restrict__ x,
                                              const float* __restrict__ W1) {
    int gw = (blockIdx.x * blockDim.x + threadIdx.x) >> 5;
    if (gw >= N_NODES) return;
    int lane = threadIdx.x & 31;
    int cnt = g_cnt[gw];
    const int* slots = &g_slot[gw * CAP];
    const int off = lane * 4;

    // hoisted: per-dim coefficients (Wa - Wb) and node features for inline A1
    float4 wa0 = *(const float4*)&W1[0 * D1 + off];
    float4 wa1 = *(const float4*)&W1[1 * D1 + off];
    float4 wa2 = *(const float4*)&W1[2 * D1 + off];
    float4 wb0 = *(const float4*)&W1[3 * D1 + off];
    float4 wb1 = *(const float4*)&W1[4 * D1 + off];
    float4 wb2 = *(const float4*)&W1[5 * D1 + off];
    float x0 = x[gw * 3 + 0], x1 = x[gw * 3 + 1], x2 = x[gw * 3 + 2];
    float4 bb = *(const float4*)&b1[off];

    __nv_bfloat162 ninf = __floats2bfloat162_rn(-INFINITY, -INFINITY);
    __nv_bfloat162 m0 = ninf, m1 = ninf;
    int j = 0;
    for (; j + 16 <= cnt; j += 16) {
        uint2 v[16];
        #pragma unroll
        for (int q = 0; q < 4; q++) {
            int4 sv = *(const int4*)&slots[j + q * 4];
            v[q * 4 + 0] = *(const uint2*)&g_B1h[sv.x * D1 + off];
            v[q * 4 + 1] = *(const uint2*)&g_B1h[sv.y * D1 + off];
            v[q * 4 + 2] = *(const uint2*)&g_B1h[sv.z * D1 + off];
            v[q * 4 + 3] = *(const uint2*)&g_B1h[sv.w * D1 + off];
        }
        #pragma unroll
        for (int u = 0; u < 16; u++) { m0 = bmax(m0, v[u].x); m1 = bmax(m1, v[u].y); }
    }
    for (; j + 4 <= cnt; j += 4) {
        int4 sv = *(const int4*)&slots[j];
        uint2 v0 = *(const uint2*)&g_B1h[sv.x * D1 + off];
        uint2 v1 = *(const uint2*)&g_B1h[sv.y * D1 + off];
        uint2 v2 = *(const uint2*)&g_B1h[sv.z * D1 + off];
        uint2 v3 = *(const uint2*)&g_B1h[sv.w * D1 + off];
        m0 = bmax(bmax(bmax(bmax(m0, v0.x), v1.x), v2.x), v3.x);
        m1 = bmax(bmax(bmax(bmax(m1, v0.y), v1.y), v2.y), v3.y);
    }
    for (; j < cnt; j++) {
        int s = slots[j];
        uint2 v = *(const uint2*)&g_B1h[s * D1 + off];
        m0 = bmax(m0, v.x);
        m1 = bmax(m1, v.y);
    }
    float h0 = 0.f, h1v = 0.f, h2 = 0.f, h3 = 0.f;
    if (cnt > 0) {
        float ax = x0 * (wa0.x - wb0.x) + x1 * (wa1.x - wb1.x) + x2 * (wa2.x - wb2.x);
        float ay = x0 * (wa0.y - wb0.y) + x1 * (wa1.y - wb1.y) + x2 * (wa2.y - wb2.y);
        float az = x0 * (wa0.z - wb0.z) + x1 * (wa1.z - wb1.z) + x2 * (wa2.z - wb2.z);
        float aw = x0 * (wa0.w - wb0.w) + x1 * (wa1.w - wb1.w) + x2 * (wa2.w - wb2.w);
        h0  = sigmoidf(ax + bb.x + __bfloat162float(__low2bfloat16(m0)));
        h1v = sigmoidf(ay + bb.y + __bfloat162float(__high2bfloat16(m0)));
        h2  = sigmoidf(az + bb.z + __bfloat162float(__low2bfloat16(m1)));
        h3  = sigmoidf(aw + bb.w + __bfloat162float(__high2bfloat16(m1)));
    }
    __nv_bfloat162 o0 = __floats2bfloat162_rn(h0, h1v);
    __nv_bfloat162 o1 = __floats2bfloat162_rn(h2, h3);
    uint2 o;
    o.x = *(unsigned int*)&o0;
    o.y = *(unsigned int*)&o1;
    *(uint2*)&g_h1[gw * D1 + off] = o;
}

// ---------------- kernel 2: GEMM2 bf16 WMMA, 64x(64+64) block, paired n-tiles, BK=64 ------
__global__ __launch_bounds__(128) void k_gemm2() {
    __shared__ __nv_bfloat16 As[64 * 72];      // [m][k-chunk] pad 72
    __shared__ __nv_bfloat16 Bs0[64 * 72];     // [k][n] A-half cols
    __shared__ __nv_bfloat16 Bs1[64 * 72];     // [k][n] B-half cols
    const int tid = threadIdx.x;               // 0..127
    const int bm = blockIdx.x * 64;
    const int n0 = blockIdx.y * 64;            // 0..192
    const int warp = tid >> 5;
    const int lane = tid & 31;
    const int wm = (warp & 1) * 32;
    const int wn = (warp >> 1) * 32;

    wmma::fragment<wmma::accumulator, 16, 16, 16, float> acc0[2][2], acc1[2][2];
    #pragma unroll
    for (int i = 0; i < 2; i++)
        #pragma unroll
        for (int j = 0; j < 2; j++) {
            wmma::fill_fragment(acc0[i][j], 0.0f);
            wmma::fill_fragment(acc1[i][j], 0.0f);
        }

    #pragma unroll
    for (int kc = 0; kc < 128; kc += 64) {
        #pragma unroll
        for (int r = 0; r < 4; r++) {
            int f = tid + r * 128;
            int m = f >> 3;
            int q = f & 7;
            float4 v = *(const float4*)&g_h1[(bm + m) * D1 + kc + q * 8];
            *(float4*)&As[m * 72 + q * 8] = v;
        }
        #pragma unroll
        for (int r = 0; r < 4; r++) {
            int f = tid + r * 128;
            int k = f >> 3;
            int q = f & 7;
            float4 v0 = *(const float4*)&g_Wcat[(kc + k) * 512 + n0 + q * 8];
            float4 v1 = *(const float4*)&g_Wcat[(kc + k) * 512 + n0 + 256 + q * 8];
            *(float4*)&Bs0[k * 72 + q * 8] = v0;
            *(float4*)&Bs1[k * 72 + q * 8] = v1;
        }
        __syncthreads();
        #pragma unroll
        for (int kk = 0; kk < 64; kk += 16) {
            wmma::fragment<wmma::matrix_a, 16, 16, 16, __nv_bfloat16, wmma::row_major> a[2];
            wmma::fragment<wmma::matrix_b, 16, 16, 16, __nv_bfloat16, wmma::row_major> b0[2], b1[2];
            #pragma unroll
            for (int i = 0; i < 2; i++)
                wmma::load_matrix_sync(a[i], &As[(wm + i * 16) * 72 + kk], 72);
            #pragma unroll
            for (int j = 0; j < 2; j++) {
                wmma::load_matrix_sync(b0[j], &Bs0[kk * 72 + wn + j * 16], 72);
                wmma::load_matrix_sync(b1[j], &Bs1[kk * 72 + wn + j * 16], 72);
            }
            #pragma unroll
            for (int i = 0; i < 2; i++)
                #pragma unroll
                for (int j = 0; j < 2; j++) {
                    wmma::mma_sync(acc0[i][j], a[i], b0[j], acc0[i][j]);
                    wmma::mma_sync(acc1[i][j], a[i], b1[j], acc1[i][j]);
                }
        }
        __syncthreads();
    }

    #pragma unroll
    for (int i = 0; i < 2; i++)
        #pragma unroll
        for (int j = 0; j < 2; j++)
            wmma::store_matrix_sync(&g_C2A[(bm + wm + i * 16) * 256 + n0 + wn + j * 16],
                                    acc0[i][j], 256, wmma::mem_row_major);
    float* cs = (float*)As + warp * 256;
    #pragma unroll
    for (int i = 0; i < 2; i++)
        #pragma unroll
        for (int j = 0; j < 2; j++) {
            wmma::store_matrix_sync(cs, acc1[i][j], 16, wmma::mem_row_major);
            __syncwarp();
            int r = lane >> 1;
            int cb = (lane & 1) * 8;
            int mrow = bm + wm + i * 16 + r;
            int ncol = n0 + wn + j * 16 + cb;
            const float* src = &cs[r * 16 + cb];
            __nv_bfloat16* dst = &g_B2h[mrow * 256 + ncol];
            #pragma unroll
            for (int u = 0; u < 4; u++) {
                __nv_bfloat162 p = __floats2bfloat162_rn(src[u * 2], src[u * 2 + 1]);
                *(__nv_bfloat162*)&dst[u * 2] = p;
            }
            __syncwarp();
        }
}

// ---------------- kernel 3: aggregate layer 2 + graph max-pool (2 warps/node) ----------------
// EXACT R8/R11 configuration (best measured: ~35 us). Do not perturb.
__global__ __launch_bounds__(256) void k_agg2_pool(const float* __restrict__ b2,
                                                   const int* __restrict__ batch) {
    int gw = (blockIdx.x * blockDim.x + threadIdx.x) >> 5;
    int node = gw >> 1;
    if (node >= N_NODES) return;
    int half = gw & 1;
    int lane = threadIdx.x & 31;
    int cnt = g_cnt[node];
    if (cnt == 0) return;
    const int* slots = &g_slot[node * CAP];
    const int off = half * 128 + lane * 4;

    __nv_bfloat162 ninf = __floats2bfloat162_rn(-INFINITY, -INFINITY);
    __nv_bfloat162 m0 = ninf, m1 = ninf;
    int j = 0;
    for (; j + 8 <= cnt; j += 8) {
        int4 sa = *(const int4*)&slots[j];
        int4 sb = *(const int4*)&slots[j + 4];
        uint2 v0 = *(const uint2*)&g_B2h[sa.x * 256 + off];
        uint2 v1 = *(const uint2*)&g_B2h[sa.y * 256 + off];
        uint2 v2 = *(const uint2*)&g_B2h[sa.z * 256 + off];
        uint2 v3 = *(const uint2*)&g_B2h[sa.w * 256 + off];
        uint2 v4 = *(const uint2*)&g_B2h[sb.x * 256 + off];
        uint2 v5 = *(const uint2*)&g_B2h[sb.y * 256 + off];
        uint2 v6 = *(const uint2*)&g_B2h[sb.z * 256 + off];
        uint2 v7 = *(const uint2*)&g_B2h[sb.w * 256 + off];
        m0 = __hmax2(m0, __hmax2(
                 __hmax2(__hmax2(*(__nv_bfloat162*)&v0.x, *(__nv_bfloat162*)&v1.x),
                         __hmax2(*(__nv_bfloat162*)&v2.x, *(__nv_bfloat162*)&v3.x)),
                 __hmax2(__hmax2(*(__nv_bfloat162*)&v4.x, *(__nv_bfloat162*)&v5.x),
                         __hmax2(*(__nv_bfloat162*)&v6.x, *(__nv_bfloat162*)&v7.x))));
        m1 = __hmax2(m1, __hmax2(
                 __hmax2(__hmax2(*(__nv_bfloat162*)&v0.y, *(__nv_bfloat162*)&v1.y),
                         __hmax2(*(__nv_bfloat162*)&v2.y, *(__nv_bfloat162*)&v3.y)),
                 __hmax2(__hmax2(*(__nv_bfloat162*)&v4.y, *(__nv_bfloat162*)&v5.y),
                         __hmax2(*(__nv_bfloat162*)&v6.y, *(__nv_bfloat162*)&v7.y))));
    }
    for (; j < cnt; j++) {
        int s = slots[j];
        uint2 v = *(const uint2*)&g_B2h[s * 256 + off];
        m0 = __hmax2(m0, *(__nv_bfloat162*)&v.x);
        m1 = __hmax2(m1, *(__nv_bfloat162*)&v.y);
    }
    float4 p = *(const float4*)&g_C2A[node * 256 + off];
    float4 q = *(const float4*)&b2[off];
    float h0 = sigmoidf(p.x + q.x + __bfloat162float(__low2bfloat16(m0)));
    float h1 = sigmoidf(p.y + q.y + __bfloat162float(__high2bfloat16(m0)));
    float h2 = sigmoidf(p.z + q.z + __bfloat162float(__low2bfloat16(m1)));
    float h3 = sigmoidf(p.w + q.w + __bfloat162float(__high2bfloat16(m1)));
    int b = batch[node];
    int* pool = (int*)&g_pool[b * D2 + off];
    atomicMax(&pool[0], __float_as_int(h0));
    atomicMax(&pool[1], __float_as_int(h1));
    atomicMax(&pool[2], __float_as_int(h2));
    atomicMax(&pool[3], __float_as_int(h3));
}

// ---------------- kernel 4: final MLP + state reset for next call ----------------
__global__ void k_mlp(const float* __restrict__ W3, const float* __restrict__ b3,
                      const float* __restrict__ W4, const float* __restrict__ b4,
                      float* __restrict__ out) {
    __shared__ float grow[256];
    __shared__ float tv[128];
    int b = blockIdx.x;
    int t = threadIdx.x;
    grow[t] = g_pool[b * D2 + t];
    grow[t + 128] = g_pool[b * D2 + t + 128];
    __syncthreads();
    g_pool[b * D2 + t] = 0.0f;
    g_pool[b * D2 + t + 128] = 0.0f;
    for (int i = b * 128 + t; i < N_NODES; i += N_GRAPHS * 128) g_cnt[i] = 0;

    float s = b3[t];
    #pragma unroll 8
    for (int k = 0; k < 256; k++)
        s += grow[k] * W3[k * 128 + t];
    tv[t] = sigmoidf(s);
    __syncthreads();
    if (t < 10) {
        float o = b4[t];
        #pragma unroll 8
        for (int d = 0; d < 128; d++)
            o += tv[d] * W4[d * 10 + t];
        out[b * 10 + t] = o;
    }
}

// ---------------- launch ----------------
extern "C" void kernel_launch(void* const* d_in, const int* in_sizes, int n_in,
                              void* d_out, int out_size) {
    const float* x  = (const float*)d_in[0];
    const int*   ei = (const int*)d_in[1];
    const int*   bt = (const int*)d_in[2];
    const float* W1 = (const float*)d_in[3];
    const float* b1 = (const float*)d_in[4];
    const float* W2 = (const float*)d_in[5];
    const float* b2 = (const float*)d_in[6];
    const float* W3 = (const float*)d_in[7];
    const float* b3 = (const float*)d_in[8];
    const float* W4 = (const float*)d_in[9];
    const float* b4 = (const float*)d_in[10];
    float* out = (float*)d_out;

    k_prep<<<640, 256>>>(x, W1, W2, ei);                      // launch 0
    k_agg1<<<(N_NODES * 32 + 255) / 256, 256>>>(b1, x, W1);   // launch 1
    dim3 g2(M_PAD / 64, 4);
    k_gemm2<<<g2, 128>>>();                                   // launch 2
    k_agg2_pool<<<(N_NODES * 64 + 255) / 256, 256>>>(b2, bt); // launch 3 (ncu sample)
    k_mlp<<<N_GRAPHS, 128>>>(W3, b3, W4, b4, out);            // launch 4
}

// round 14
// speedup vs baseline: 1.0291x; 1.0203x over previous
#include <cuda_runtime.h>
#include <cuda_bf16.h>
#include <math.h>
#include <mma.h>

using namespace nvcuda;

#define N_NODES  10000
#define M_PAD    10112          // 158 * 64
#define N_EDGES  320000
#define N_GRAPHS 64
#define D1 128
#define D2 256
#define CAP 128                 // per-node slot capacity (Poisson(32), max ~57)

// ---------------- scratch (zero-initialized at load; self-cleaning per call) ----------------
__device__ int            g_cnt[N_NODES];            // reset by k_mlp each call
__device__ int            g_slot[N_NODES * CAP];
__device__ float          g_A1[N_NODES * D1];
__device__ __nv_bfloat16  g_B1h[N_NODES * D1];       // bf16 gather table, layer 1
__device__ __nv_bfloat16  g_h1[M_PAD * D1];          // pad rows stay 0 forever
__device__ __nv_bfloat16  g_Wcat[128 * 512];         // bf16 [k][n]: n<256 -> W2a-W2b else W2b
__device__ float          g_C2A[M_PAD * 256];        // fp32 A2 (self term)
__device__ __nv_bfloat16  g_B2h[M_PAD * 256];        // bf16 gather table, layer 2
__device__ float          g_pool[N_GRAPHS * D2];     // reset by k_mlp each call

__device__ __forceinline__ float sigmoidf(float x) {
    return 1.0f / (1.0f + __expf(-x));
}
__device__ __forceinline__ __nv_bfloat162 bmax(__nv_bfloat162 a, unsigned int b) {
    return __hmax2(a, *(__nv_bfloat162*)&b);
}

// ---------------- kernel 0: prep = gemm1 + wcat + edge scatter (R12 config) ----------------
__global__ __launch_bounds__(256) void k_prep(const float* __restrict__ x,
                                              const float* __restrict__ W1,
                                              const float* __restrict__ W2,
                                              const int* __restrict__ ei) {
    int i = blockIdx.x * blockDim.x + threadIdx.x;
    int stride = gridDim.x * blockDim.x;
    for (int idx = i; idx < N_NODES * D1; idx += stride) {
        int n = idx >> 7;
        int d = idx & 127;
        float x0 = x[n * 3 + 0], x1 = x[n * 3 + 1], x2 = x[n * 3 + 2];
        float wb0 = W1[3 * D1 + d], wb1 = W1[4 * D1 + d], wb2 = W1[5 * D1 + d];
        float wa0 = W1[0 * D1 + d], wa1 = W1[1 * D1 + d], wa2 = W1[2 * D1 + d];
        g_B1h[idx] = __float2bfloat16(x0 * wb0 + x1 * wb1 + x2 * wb2);
        g_A1[idx]  = x0 * (wa0 - wb0) + x1 * (wa1 - wb1) + x2 * (wa2 - wb2);
    }
    for (int idx = i; idx < 128 * 512; idx += stride) {
        int k = idx >> 9;
        int n = idx & 511;
        float v;
        if (n < 256) v = W2[k * 256 + n] - W2[(128 + k) * 256 + n];
        else         v = W2[(128 + k) * 256 + (n - 256)];
        g_Wcat[idx] = __float2bfloat16(v);
    }
    for (int t = i; t < N_EDGES / 2; t += stride) {
        int e = t * 2;
        int2 s = *(const int2*)&ei[e];
        int2 d = *(const int2*)&ei[N_EDGES + e];
        int p0 = atomicAdd(&g_cnt[d.x], 1);
        g_slot[d.x * CAP + p0] = s.x;
        int p1 = atomicAdd(&g_cnt[d.y], 1);
        g_slot[d.y * CAP + p1] = s.y;
    }
}

// ---------------- kernel 1: aggregate layer 1 -> h1 bf16 (warp/node, unroll 16, A1 table) ---
__global__ __launch_bounds__(256) void k_agg1(const float* __restrict__ b1) {
    int gw = (blockIdx.x * blockDim.x + threadIdx.x) >> 5;
    if (gw >= N_NODES) return;
    int lane = threadIdx.x & 31;
    int cnt = g_cnt[gw];
    const int* slots = &g_slot[gw * CAP];
    const int off = lane * 4;

    __nv_bfloat162 ninf = __floats2bfloat162_rn(-INFINITY, -INFINITY);
    __nv_bfloat162 m0 = ninf, m1 = ninf;
    int j = 0;
    for (; j + 16 <= cnt; j += 16) {
        uint2 v[16];
        #pragma unroll
        for (int q = 0; q < 4; q++) {
            int4 sv = *(const int4*)&slots[j + q * 4];
            v[q * 4 + 0] = *(const uint2*)&g_B1h[sv.x * D1 + off];
            v[q * 4 + 1] = *(const uint2*)&g_B1h[sv.y * D1 + off];
            v[q * 4 + 2] = *(const uint2*)&g_B1h[sv.z * D1 + off];
            v[q * 4 + 3] = *(const uint2*)&g_B1h[sv.w * D1 + off];
        }
        #pragma unroll
        for (int u = 0; u < 16; u++) { m0 = bmax(m0, v[u].x); m1 = bmax(m1, v[u].y); }
    }
    for (; j + 4 <= cnt; j += 4) {
        int4 sv = *(const int4*)&slots[j];
        uint2 v0 = *(const uint2*)&g_B1h[sv.x * D1 + off];
        uint2 v1 = *(const uint2*)&g_B1h[sv.y * D1 + off];
        uint2 v2 = *(const uint2*)&g_B1h[sv.z * D1 + off];
        uint2 v3 = *(const uint2*)&g_B1h[sv.w * D1 + off];
        m0 = bmax(bmax(bmax(bmax(m0, v0.x), v1.x), v2.x), v3.x);
        m1 = bmax(bmax(bmax(bmax(m1, v0.y), v1.y), v2.y), v3.y);
    }
    for (; j < cnt; j++) {
        int s = slots[j];
        uint2 v = *(const uint2*)&g_B1h[s * D1 + off];
        m0 = bmax(m0, v.x);
        m1 = bmax(m1, v.y);
    }
    float h0 = 0.f, h1v = 0.f, h2 = 0.f, h3 = 0.f;
    if (cnt > 0) {
        float4 a  = *(const float4*)&g_A1[gw * D1 + off];
        float4 bb = *(const float4*)&b1[off];
        h0  = sigmoidf(a.x + bb.x + __bfloat162float(__low2bfloat16(m0)));
        h1v = sigmoidf(a.y + bb.y + __bfloat162float(__high2bfloat16(m0)));
        h2  = sigmoidf(a.z + bb.z + __bfloat162float(__low2bfloat16(m1)));
        h3  = sigmoidf(a.w + bb.w + __bfloat162float(__high2bfloat16(m1)));
    }
    __nv_bfloat162 o0 = __floats2bfloat162_rn(h0, h1v);
    __nv_bfloat162 o1 = __floats2bfloat162_rn(h2, h3);
    uint2 o;
    o.x = *(unsigned int*)&o0;
    o.y = *(unsigned int*)&o1;
    *(uint2*)&g_h1[gw * D1 + off] = o;
}

// ---------------- kernel 2: GEMM2 bf16 WMMA, 64x(64+64) block, paired n-tiles, BK=64 ------
__global__ __launch_bounds__(128) void k_gemm2() {
    __shared__ __nv_bfloat16 As[64 * 72];      // [m][k-chunk] pad 72
    __shared__ __nv_bfloat16 Bs0[64 * 72];     // [k][n] A-half cols
    __shared__ __nv_bfloat16 Bs1[64 * 72];     // [k][n] B-half cols
    const int tid = threadIdx.x;               // 0..127
    const int bm = blockIdx.x * 64;
    const int n0 = blockIdx.y * 64;            // 0..192
    const int warp = tid >> 5;
    const int lane = tid & 31;
    const int wm = (warp & 1) * 32;
    const int wn = (warp >> 1) * 32;

    wmma::fragment<wmma::accumulator, 16, 16, 16, float> acc0[2][2], acc1[2][2];
    #pragma unroll
    for (int i = 0; i < 2; i++)
        #pragma unroll
        for (int j = 0; j < 2; j++) {
            wmma::fill_fragment(acc0[i][j], 0.0f);
            wmma::fill_fragment(acc1[i][j], 0.0f);
        }

    #pragma unroll
    for (int kc = 0; kc < 128; kc += 64) {
        #pragma unroll
        for (int r = 0; r < 4; r++) {
            int f = tid + r * 128;
            int m = f >> 3;
            int q = f & 7;
            float4 v = *(const float4*)&g_h1[(bm + m) * D1 + kc + q * 8];
            *(float4*)&As[m * 72 + q * 8] = v;
        }
        #pragma unroll
        for (int r = 0; r < 4; r++) {
            int f = tid + r * 128;
            int k = f >> 3;
            int q = f & 7;
            float4 v0 = *(const float4*)&g_Wcat[(kc + k) * 512 + n0 + q * 8];
            float4 v1 = *(const float4*)&g_Wcat[(kc + k) * 512 + n0 + 256 + q * 8];
            *(float4*)&Bs0[k * 72 + q * 8] = v0;
            *(float4*)&Bs1[k * 72 + q * 8] = v1;
        }
        __syncthreads();
        #pragma unroll
        for (int kk = 0; kk < 64; kk += 16) {
            wmma::fragment<wmma::matrix_a, 16, 16, 16, __nv_bfloat16, wmma::row_major> a[2];
            wmma::fragment<wmma::matrix_b, 16, 16, 16, __nv_bfloat16, wmma::row_major> b0[2], b1[2];
            #pragma unroll
            for (int i = 0; i < 2; i++)
                wmma::load_matrix_sync(a[i], &As[(wm + i * 16) * 72 + kk], 72);
            #pragma unroll
            for (int j = 0; j < 2; j++) {
                wmma::load_matrix_sync(b0[j], &Bs0[kk * 72 + wn + j * 16], 72);
                wmma::load_matrix_sync(b1[j], &Bs1[kk * 72 + wn + j * 16], 72);
            }
            #pragma unroll
            for (int i = 0; i < 2; i++)
                #pragma unroll
                for (int j = 0; j < 2; j++) {
                    wmma::mma_sync(acc0[i][j], a[i], b0[j], acc0[i][j]);
                    wmma::mma_sync(acc1[i][j], a[i], b1[j], acc1[i][j]);
                }
        }
        __syncthreads();
    }

    #pragma unroll
    for (int i = 0; i < 2; i++)
        #pragma unroll
        for (int j = 0; j < 2; j++)
            wmma::store_matrix_sync(&g_C2A[(bm + wm + i * 16) * 256 + n0 + wn + j * 16],
                                    acc0[i][j], 256, wmma::mem_row_major);
    float* cs = (float*)As + warp * 256;
    #pragma unroll
    for (int i = 0; i < 2; i++)
        #pragma unroll
        for (int j = 0; j < 2; j++) {
            wmma::store_matrix_sync(cs, acc1[i][j], 16, wmma::mem_row_major);
            __syncwarp();
            int r = lane >> 1;
            int cb = (lane & 1) * 8;
            int mrow = bm + wm + i * 16 + r;
            int ncol = n0 + wn + j * 16 + cb;
            const float* src = &cs[r * 16 + cb];
            __nv_bfloat16* dst = &g_B2h[mrow * 256 + ncol];
            #pragma unroll
            for (int u = 0; u < 4; u++) {
                __nv_bfloat162 p = __floats2bfloat162_rn(src[u * 2], src[u * 2 + 1]);
                *(__nv_bfloat162*)&dst[u * 2] = p;
            }
            __syncwarp();
        }
}

// ---------------- kernel 3: aggregate layer 2 + graph max-pool (2 warps/node) ----------------
// EXACT R8 configuration (best measured: ~35 us across 4 rounds). Do not perturb.
__global__ __launch_bounds__(256) void k_agg2_pool(const float* __restrict__ b2,
                                                   const int* __restrict__ batch) {
    int gw = (blockIdx.x * blockDim.x + threadIdx.x) >> 5;
    int node = gw >> 1;
    if (node >= N_NODES) return;
    int half = gw & 1;
    int lane = threadIdx.x & 31;
    int cnt = g_cnt[node];
    if (cnt == 0) return;
    const int* slots = &g_slot[node * CAP];
    const int off = half * 128 + lane * 4;

    __nv_bfloat162 ninf = __floats2bfloat162_rn(-INFINITY, -INFINITY);
    __nv_bfloat162 m0 = ninf, m1 = ninf;
    int j = 0;
    for (; j + 8 <= cnt; j += 8) {
        int4 sa = *(const int4*)&slots[j];
        int4 sb = *(const int4*)&slots[j + 4];
        uint2 v0 = *(const uint2*)&g_B2h[sa.x * 256 + off];
        uint2 v1 = *(const uint2*)&g_B2h[sa.y * 256 + off];
        uint2 v2 = *(const uint2*)&g_B2h[sa.z * 256 + off];
        uint2 v3 = *(const uint2*)&g_B2h[sa.w * 256 + off];
        uint2 v4 = *(const uint2*)&g_B2h[sb.x * 256 + off];
        uint2 v5 = *(const uint2*)&g_B2h[sb.y * 256 + off];
        uint2 v6 = *(const uint2*)&g_B2h[sb.z * 256 + off];
        uint2 v7 = *(const uint2*)&g_B2h[sb.w * 256 + off];
        m0 = __hmax2(m0, __hmax2(
                 __hmax2(__hmax2(*(__nv_bfloat162*)&v0.x, *(__nv_bfloat162*)&v1.x),
                         __hmax2(*(__nv_bfloat162*)&v2.x, *(__nv_bfloat162*)&v3.x)),
                 __hmax2(__hmax2(*(__nv_bfloat162*)&v4.x, *(__nv_bfloat162*)&v5.x),
                         __hmax2(*(__nv_bfloat162*)&v6.x, *(__nv_bfloat162*)&v7.x))));
        m1 = __hmax2(m1, __hmax2(
                 __hmax2(__hmax2(*(__nv_bfloat162*)&v0.y, *(__nv_bfloat162*)&v1.y),
                         __hmax2(*(__nv_bfloat162*)&v2.y, *(__nv_bfloat162*)&v3.y)),
                 __hmax2(__hmax2(*(__nv_bfloat162*)&v4.y, *(__nv_bfloat162*)&v5.y),
                         __hmax2(*(__nv_bfloat162*)&v6.y, *(__nv_bfloat162*)&v7.y))));
    }
    for (; j < cnt; j++) {
        int s = slots[j];
        uint2 v = *(const uint2*)&g_B2h[s * 256 + off];
        m0 = __hmax2(m0, *(__nv_bfloat162*)&v.x);
        m1 = __hmax2(m1, *(__nv_bfloat162*)&v.y);
    }
    float4 p = *(const float4*)&g_C2A[node * 256 + off];
    float4 q = *(const float4*)&b2[off];
    float h0 = sigmoidf(p.x + q.x + __bfloat162float(__low2bfloat16(m0)));
    float h1 = sigmoidf(p.y + q.y + __bfloat162float(__high2bfloat16(m0)));
    float h2 = sigmoidf(p.z + q.z + __bfloat162float(__low2bfloat16(m1)));
    float h3 = sigmoidf(p.w + q.w + __bfloat162float(__high2bfloat16(m1)));
    int b = batch[node];
    int* pool = (int*)&g_pool[b * D2 + off];
    atomicMax(&pool[0], __float_as_int(h0));
    atomicMax(&pool[1], __float_as_int(h1));
    atomicMax(&pool[2], __float_as_int(h2));
    atomicMax(&pool[3], __float_as_int(h3));
}

// ---------------- kernel 4: final MLP + state reset for next call ----------------
__global__ void k_mlp(const float* __restrict__ W3, const float* __restrict__ b3,
                      const float* __restrict__ W4, const float* __restrict__ b4,
                      float* __restrict__ out) {
    __shared__ float grow[256];
    __shared__ float tv[128];
    int b = blockIdx.x;
    int t = threadIdx.x;
    grow[t] = g_pool[b * D2 + t];
    grow[t + 128] = g_pool[b * D2 + t + 128];
    __syncthreads();
    g_pool[b * D2 + t] = 0.0f;
    g_pool[b * D2 + t + 128] = 0.0f;
    for (int i = b * 128 + t; i < N_NODES; i += N_GRAPHS * 128) g_cnt[i] = 0;

    float s = b3[t];
    #pragma unroll 8
    for (int k = 0; k < 256; k++)
        s += grow[k] * W3[k * 128 + t];
    tv[t] = sigmoidf(s);
    __syncthreads();
    if (t < 10) {
        float o = b4[t];
        #pragma unroll 8
        for (int d = 0; d < 128; d++)
            o += tv[d] * W4[d * 10 + t];
        out[b * 10 + t] = o;
    }
}

// ---------------- launch ----------------
extern "C" void kernel_launch(void* const* d_in, const int* in_sizes, int n_in,
                              void* d_out, int out_size) {
    const float* x  = (const float*)d_in[0];
    const int*   ei = (const int*)d_in[1];
    const int*   bt = (const int*)d_in[2];
    const float* W1 = (const float*)d_in[3];
    const float* b1 = (const float*)d_in[4];
    const float* W2 = (const float*)d_in[5];
    const float* b2 = (const float*)d_in[6];
    const float* W3 = (const float*)d_in[7];
    const float* b3 = (const float*)d_in[8];
    const float* W4 = (const float*)d_in[9];
    const float* b4 = (const float*)d_in[10];
    float* out = (float*)d_out;

    k_prep<<<640, 256>>>(x, W1, W2, ei);                      // launch 0
    k_agg1<<<(N_NODES * 32 + 255) / 256, 256>>>(b1);          // launch 1
    dim3 g2(M_PAD / 64, 4);
    k_gemm2<<<g2, 128>>>();                                   // launch 2
    k_agg2_pool<<<(N_NODES * 64 + 255) / 256, 256>>>(b2, bt); // launch 3 (ncu sample)
    k_mlp<<<N_GRAPHS, 128>>>(W3, b3, W4, b4, out);            // launch 4
}

// round 15
// speedup vs baseline: 1.0336x; 1.0044x over previous
#include <cuda_runtime.h>
#include <cuda_bf16.h>
#include <math.h>
#include <mma.h>

using namespace nvcuda;

#define N_NODES  10000
#define M_PAD    10112          // 158 * 64
#define N_EDGES  320000
#define N_GRAPHS 64
#define D1 128
#define D2 256
#define CAP 128                 // per-node slot capacity (Poisson(32), max ~57)

// ---------------- scratch (zero-initialized at load; self-cleaning per call) ----------------
__device__ int            g_cnt[N_NODES];            // reset by k_mlp each call
__device__ int            g_slot[N_NODES * CAP];
__device__ __nv_bfloat16  g_A1b[N_NODES * D1];       // bf16 self term with b1 pre-folded
__device__ __nv_bfloat16  g_B1h[N_NODES * D1];       // bf16 gather table, layer 1
__device__ __nv_bfloat16  g_h1[M_PAD * D1];          // pad rows stay 0 forever
__device__ __nv_bfloat16  g_Wcat[128 * 512];         // bf16 [k][n]: n<256 -> W2a-W2b else W2b
__device__ float          g_C2A[M_PAD * 256];        // fp32 A2 (self term)
__device__ __nv_bfloat16  g_B2h[M_PAD * 256];        // bf16 gather table, layer 2
__device__ float          g_pool[N_GRAPHS * D2];     // reset by k_mlp each call

__device__ __forceinline__ float sigmoidf(float x) {
    return 1.0f / (1.0f + __expf(-x));
}
__device__ __forceinline__ __nv_bfloat162 bmax(__nv_bfloat162 a, unsigned int b) {
    return __hmax2(a, *(__nv_bfloat162*)&b);
}

// ---------------- kernel 0: prep = gemm1 (A1b bf16, b1 folded) + wcat + edge scatter -------
__global__ __launch_bounds__(256) void k_prep(const float* __restrict__ x,
                                              const float* __restrict__ W1,
                                              const float* __restrict__ b1,
                                              const float* __restrict__ W2,
                                              const int* __restrict__ ei) {
    int i = blockIdx.x * blockDim.x + threadIdx.x;
    int stride = gridDim.x * blockDim.x;
    for (int idx = i; idx < N_NODES * D1; idx += stride) {
        int n = idx >> 7;
        int d = idx & 127;
        float x0 = x[n * 3 + 0], x1 = x[n * 3 + 1], x2 = x[n * 3 + 2];
        float wb0 = W1[3 * D1 + d], wb1 = W1[4 * D1 + d], wb2 = W1[5 * D1 + d];
        float wa0 = W1[0 * D1 + d], wa1 = W1[1 * D1 + d], wa2 = W1[2 * D1 + d];
        g_B1h[idx] = __float2bfloat16(x0 * wb0 + x1 * wb1 + x2 * wb2);
        float a = x0 * (wa0 - wb0) + x1 * (wa1 - wb1) + x2 * (wa2 - wb2);
        g_A1b[idx] = __float2bfloat16(a + b1[d]);
    }
    for (int idx = i; idx < 128 * 512; idx += stride) {
        int k = idx >> 9;
        int n = idx & 511;
        float v;
        if (n < 256) v = W2[k * 256 + n] - W2[(128 + k) * 256 + n];
        else         v = W2[(128 + k) * 256 + (n - 256)];
        g_Wcat[idx] = __float2bfloat16(v);
    }
    for (int t = i; t < N_EDGES / 2; t += stride) {
        int e = t * 2;
        int2 s = *(const int2*)&ei[e];
        int2 d = *(const int2*)&ei[N_EDGES + e];
        int p0 = atomicAdd(&g_cnt[d.x], 1);
        g_slot[d.x * CAP + p0] = s.x;
        int p1 = atomicAdd(&g_cnt[d.y], 1);
        g_slot[d.y * CAP + p1] = s.y;
    }
}

// ---------------- kernel 1: aggregate layer 1 -> h1 bf16 (warp/node, unroll 16) ------------
__global__ __launch_bounds__(256) void k_agg1() {
    int gw = (blockIdx.x * blockDim.x + threadIdx.x) >> 5;
    if (gw >= N_NODES) return;
    int lane = threadIdx.x & 31;
    int cnt = g_cnt[gw];
    const int* slots = &g_slot[gw * CAP];
    const int off = lane * 4;

    __nv_bfloat162 ninf = __floats2bfloat162_rn(-INFINITY, -INFINITY);
    __nv_bfloat162 m0 = ninf, m1 = ninf;
    int j = 0;
    for (; j + 16 <= cnt; j += 16) {
        uint2 v[16];
        #pragma unroll
        for (int q = 0; q < 4; q++) {
            int4 sv = *(const int4*)&slots[j + q * 4];
            v[q * 4 + 0] = *(const uint2*)&g_B1h[sv.x * D1 + off];
            v[q * 4 + 1] = *(const uint2*)&g_B1h[sv.y * D1 + off];
            v[q * 4 + 2] = *(const uint2*)&g_B1h[sv.z * D1 + off];
            v[q * 4 + 3] = *(const uint2*)&g_B1h[sv.w * D1 + off];
        }
        #pragma unroll
        for (int u = 0; u < 16; u++) { m0 = bmax(m0, v[u].x); m1 = bmax(m1, v[u].y); }
    }
    for (; j + 4 <= cnt; j += 4) {
        int4 sv = *(const int4*)&slots[j];
        uint2 v0 = *(const uint2*)&g_B1h[sv.x * D1 + off];
        uint2 v1 = *(const uint2*)&g_B1h[sv.y * D1 + off];
        uint2 v2 = *(const uint2*)&g_B1h[sv.z * D1 + off];
        uint2 v3 = *(const uint2*)&g_B1h[sv.w * D1 + off];
        m0 = bmax(bmax(bmax(bmax(m0, v0.x), v1.x), v2.x), v3.x);
        m1 = bmax(bmax(bmax(bmax(m1, v0.y), v1.y), v2.y), v3.y);
    }
    for (; j < cnt; j++) {
        int s = slots[j];
        uint2 v = *(const uint2*)&g_B1h[s * D1 + off];
        m0 = bmax(m0, v.x);
        m1 = bmax(m1, v.y);
    }
    float h0 = 0.f, h1v = 0.f, h2 = 0.f, h3 = 0.f;
    if (cnt > 0) {
        uint2 av = *(const uint2*)&g_A1b[gw * D1 + off];
        __nv_bfloat162 a0 = *(__nv_bfloat162*)&av.x;
        __nv_bfloat162 a1 = *(__nv_bfloat162*)&av.y;
        h0  = sigmoidf(__bfloat162float(__low2bfloat16(a0))  + __bfloat162float(__low2bfloat16(m0)));
        h1v = sigmoidf(__bfloat162float(__high2bfloat16(a0)) + __bfloat162float(__high2bfloat16(m0)));
        h2  = sigmoidf(__bfloat162float(__low2bfloat16(a1))  + __bfloat162float(__low2bfloat16(m1)));
        h3  = sigmoidf(__bfloat162float(__high2bfloat16(a1)) + __bfloat162float(__high2bfloat16(m1)));
    }
    __nv_bfloat162 o0 = __floats2bfloat162_rn(h0, h1v);
    __nv_bfloat162 o1 = __floats2bfloat162_rn(h2, h3);
    uint2 o;
    o.x = *(unsigned int*)&o0;
    o.y = *(unsigned int*)&o1;
    *(uint2*)&g_h1[gw * D1 + off] = o;
}

// ---------------- kernel 2: GEMM2 bf16 WMMA, paired n-tiles, BK=64, reg double-buffer ------
__global__ __launch_bounds__(128) void k_gemm2() {
    __shared__ __nv_bfloat16 As[64 * 72];      // [m][k-chunk] pad 72
    __shared__ __nv_bfloat16 Bs0[64 * 72];     // [k][n] A-half cols
    __shared__ __nv_bfloat16 Bs1[64 * 72];     // [k][n] B-half cols
    const int tid = threadIdx.x;               // 0..127
    const int bm = blockIdx.x * 64;
    const int n0 = blockIdx.y * 64;            // 0..192
    const int warp = tid >> 5;
    const int lane = tid & 31;
    const int wm = (warp & 1) * 32;
    const int wn = (warp >> 1) * 32;

    // per-thread load coordinates (shared by both chunks)
    int mA[4], qA[4], kB[4], qB[4];
    #pragma unroll
    for (int r = 0; r < 4; r++) {
        int f = tid + r * 128;
        mA[r] = f >> 3;  qA[r] = f & 7;
        kB[r] = f >> 3;  qB[r] = f & 7;
    }

    // chunk-0 tile fill
    #pragma unroll
    for (int r = 0; r < 4; r++) {
        *(float4*)&As[mA[r] * 72 + qA[r] * 8]  = *(const float4*)&g_h1[(bm + mA[r]) * D1 + qA[r] * 8];
        *(float4*)&Bs0[kB[r] * 72 + qB[r] * 8] = *(const float4*)&g_Wcat[kB[r] * 512 + n0 + qB[r] * 8];
        *(float4*)&Bs1[kB[r] * 72 + qB[r] * 8] = *(const float4*)&g_Wcat[kB[r] * 512 + n0 + 256 + qB[r] * 8];
    }
    __syncthreads();

    // prefetch chunk-1 (kc=64) into registers — overlaps with chunk-0 mma
    float4 pa[4], pb0[4], pb1[4];
    #pragma unroll
    for (int r = 0; r < 4; r++) {
        pa[r]  = *(const float4*)&g_h1[(bm + mA[r]) * D1 + 64 + qA[r] * 8];
        pb0[r] = *(const float4*)&g_Wcat[(64 + kB[r]) * 512 + n0 + qB[r] * 8];
        pb1[r] = *(const float4*)&g_Wcat[(64 + kB[r]) * 512 + n0 + 256 + qB[r] * 8];
    }

    wmma::fragment<wmma::accumulator, 16, 16, 16, float> acc0[2][2], acc1[2][2];
    #pragma unroll
    for (int i = 0; i < 2; i++)
        #pragma unroll
        for (int j = 0; j < 2; j++) {
            wmma::fill_fragment(acc0[i][j], 0.0f);
            wmma::fill_fragment(acc1[i][j], 0.0f);
        }

    // compute chunk 0
    #pragma unroll
    for (int kk = 0; kk < 64; kk += 16) {
        wmma::fragment<wmma::matrix_a, 16, 16, 16, __nv_bfloat16, wmma::row_major> a[2];
        wmma::fragment<wmma::matrix_b, 16, 16, 16, __nv_bfloat16, wmma::row_major> b0[2], b1[2];
        #pragma unroll
        for (int i = 0; i < 2; i++)
            wmma::load_matrix_sync(a[i], &As[(wm + i * 16) * 72 + kk], 72);
        #pragma unroll
        for (int j = 0; j < 2; j++) {
            wmma::load_matrix_sync(b0[j], &Bs0[kk * 72 + wn + j * 16], 72);
            wmma::load_matrix_sync(b1[j], &Bs1[kk * 72 + wn + j * 16], 72);
        }
        #pragma unroll
        for (int i = 0; i < 2; i++)
            #pragma unroll
            for (int j = 0; j < 2; j++) {
                wmma::mma_sync(acc0[i][j], a[i], b0[j], acc0[i][j]);
                wmma::mma_sync(acc1[i][j], a[i], b1[j], acc1[i][j]);
            }
    }
    __syncthreads();
    // store chunk-1 prefetch to smem
    #pragma unroll
    for (int r = 0; r < 4; r++) {
        *(float4*)&As[mA[r] * 72 + qA[r] * 8]  = pa[r];
        *(float4*)&Bs0[kB[r] * 72 + qB[r] * 8] = pb0[r];
        *(float4*)&Bs1[kB[r] * 72 + qB[r] * 8] = pb1[r];
    }
    __syncthreads();
    // compute chunk 1
    #pragma unroll
    for (int kk = 0; kk < 64; kk += 16) {
        wmma::fragment<wmma::matrix_a, 16, 16, 16, __nv_bfloat16, wmma::row_major> a[2];
        wmma::fragment<wmma::matrix_b, 16, 16, 16, __nv_bfloat16, wmma::row_major> b0[2], b1[2];
        #pragma unroll
        for (int i = 0; i < 2; i++)
            wmma::load_matrix_sync(a[i], &As[(wm + i * 16) * 72 + kk], 72);
        #pragma unroll
        for (int j = 0; j < 2; j++) {
            wmma::load_matrix_sync(b0[j], &Bs0[kk * 72 + wn + j * 16], 72);
            wmma::load_matrix_sync(b1[j], &Bs1[kk * 72 + wn + j * 16], 72);
        }
        #pragma unroll
        for (int i = 0; i < 2; i++)
            #pragma unroll
            for (int j = 0; j < 2; j++) {
                wmma::mma_sync(acc0[i][j], a[i], b0[j], acc0[i][j]);
                wmma::mma_sync(acc1[i][j], a[i], b1[j], acc1[i][j]);
            }
    }
    __syncthreads();                           // all warps done reading As before staging reuse

    #pragma unroll
    for (int i = 0; i < 2; i++)
        #pragma unroll
        for (int j = 0; j < 2; j++)
            wmma::store_matrix_sync(&g_C2A[(bm + wm + i * 16) * 256 + n0 + wn + j * 16],
                                    acc0[i][j], 256, wmma::mem_row_major);
    float* cs = (float*)As + warp * 256;
    #pragma unroll
    for (int i = 0; i < 2; i++)
        #pragma unroll
        for (int j = 0; j < 2; j++) {
            wmma::store_matrix_sync(cs, acc1[i][j], 16, wmma::mem_row_major);
            __syncwarp();
            int r = lane >> 1;
            int cb = (lane & 1) * 8;
            int mrow = bm + wm + i * 16 + r;
            int ncol = n0 + wn + j * 16 + cb;
            const float* src = &cs[r * 16 + cb];
            __nv_bfloat16* dst = &g_B2h[mrow * 256 + ncol];
            #pragma unroll
            for (int u = 0; u < 4; u++) {
                __nv_bfloat162 p = __floats2bfloat162_rn(src[u * 2], src[u * 2 + 1]);
                *(__nv_bfloat162*)&dst[u * 2] = p;
            }
            __syncwarp();
        }
}

// ---------------- kernel 3: aggregate layer 2 + graph max-pool (2 warps/node) ----------------
// EXACT R8 configuration (best measured: ~35 us across 5 rounds). Do not perturb.
__global__ __launch_bounds__(256) void k_agg2_pool(const float* __restrict__ b2,
                                                   const int* __restrict__ batch) {
    int gw = (blockIdx.x * blockDim.x + threadIdx.x) >> 5;
    int node = gw >> 1;
    if (node >= N_NODES) return;
    int half = gw & 1;
    int lane = threadIdx.x & 31;
    int cnt = g_cnt[node];
    if (cnt == 0) return;
    const int* slots = &g_slot[node * CAP];
    const int off = half * 128 + lane * 4;

    __nv_bfloat162 ninf = __floats2bfloat162_rn(-INFINITY, -INFINITY);
    __nv_bfloat162 m0 = ninf, m1 = ninf;
    int j = 0;
    for (; j + 8 <= cnt; j += 8) {
        int4 sa = *(const int4*)&slots[j];
        int4 sb = *(const int4*)&slots[j + 4];
        uint2 v0 = *(const uint2*)&g_B2h[sa.x * 256 + off];
        uint2 v1 = *(const uint2*)&g_B2h[sa.y * 256 + off];
        uint2 v2 = *(const uint2*)&g_B2h[sa.z * 256 + off];
        uint2 v3 = *(const uint2*)&g_B2h[sa.w * 256 + off];
        uint2 v4 = *(const uint2*)&g_B2h[sb.x * 256 + off];
        uint2 v5 = *(const uint2*)&g_B2h[sb.y * 256 + off];
        uint2 v6 = *(const uint2*)&g_B2h[sb.z * 256 + off];
        uint2 v7 = *(const uint2*)&g_B2h[sb.w * 256 + off];
        m0 = __hmax2(m0, __hmax2(
                 __hmax2(__hmax2(*(__nv_bfloat162*)&v0.x, *(__nv_bfloat162*)&v1.x),
                         __hmax2(*(__nv_bfloat162*)&v2.x, *(__nv_bfloat162*)&v3.x)),
                 __hmax2(__hmax2(*(__nv_bfloat162*)&v4.x, *(__nv_bfloat162*)&v5.x),
                         __hmax2(*(__nv_bfloat162*)&v6.x, *(__nv_bfloat162*)&v7.x))));
        m1 = __hmax2(m1, __hmax2(
                 __hmax2(__hmax2(*(__nv_bfloat162*)&v0.y, *(__nv_bfloat162*)&v1.y),
                         __hmax2(*(__nv_bfloat162*)&v2.y, *(__nv_bfloat162*)&v3.y)),
                 __hmax2(__hmax2(*(__nv_bfloat162*)&v4.y, *(__nv_bfloat162*)&v5.y),
                         __hmax2(*(__nv_bfloat162*)&v6.y, *(__nv_bfloat162*)&v7.y))));
    }
    for (; j < cnt; j++) {
        int s = slots[j];
        uint2 v = *(const uint2*)&g_B2h[s * 256 + off];
        m0 = __hmax2(m0, *(__nv_bfloat162*)&v.x);
        m1 = __hmax2(m1, *(__nv_bfloat162*)&v.y);
    }
    float4 p = *(const float4*)&g_C2A[node * 256 + off];
    float4 q = *(const float4*)&b2[off];
    float h0 = sigmoidf(p.x + q.x + __bfloat162float(__low2bfloat16(m0)));
    float h1 = sigmoidf(p.y + q.y + __bfloat162float(__high2bfloat16(m0)));
    float h2 = sigmoidf(p.z + q.z + __bfloat162float(__low2bfloat16(m1)));
    float h3 = sigmoidf(p.w + q.w + __bfloat162float(__high2bfloat16(m1)));
    int b = batch[node];
    int* pool = (int*)&g_pool[b * D2 + off];
    atomicMax(&pool[0], __float_as_int(h0));
    atomicMax(&pool[1], __float_as_int(h1));
    atomicMax(&pool[2], __float_as_int(h2));
    atomicMax(&pool[3], __float_as_int(h3));
}

// ---------------- kernel 4: final MLP + state reset for next call ----------------
__global__ void k_mlp(const float* __restrict__ W3, const float* __restrict__ b3,
                      const float* __restrict__ W4, const float* __restrict__ b4,
                      float* __restrict__ out) {
    __shared__ float grow[256];
    __shared__ float tv[128];
    int b = blockIdx.x;
    int t = threadIdx.x;
    grow[t] = g_pool[b * D2 + t];
    grow[t + 128] = g_pool[b * D2 + t + 128];
    __syncthreads();
    g_pool[b * D2 + t] = 0.0f;
    g_pool[b * D2 + t + 128] = 0.0f;
    for (int i = b * 128 + t; i < N_NODES; i += N_GRAPHS * 128) g_cnt[i] = 0;

    float s = b3[t];
    #pragma unroll 8
    for (int k = 0; k < 256; k++)
        s += grow[k] * W3[k * 128 + t];
    tv[t] = sigmoidf(s);
    __syncthreads();
    if (t < 10) {
        float o = b4[t];
        #pragma unroll 8
        for (int d = 0; d < 128; d++)
            o += tv[d] * W4[d * 10 + t];
        out[b * 10 + t] = o;
    }
}

// ---------------- launch ----------------
extern "C" void kernel_launch(void* const* d_in, const int* in_sizes, int n_in,
                              void* d_out, int out_size) {
    const float* x  = (const float*)d_in[0];
    const int*   ei = (const int*)d_in[1];
    const int*   bt = (const int*)d_in[2];
    const float* W1 = (const float*)d_in[3];
    const float* b1 = (const float*)d_in[4];
    const float* W2 = (const float*)d_in[5];
    const float* b2 = (const float*)d_in[6];
    const float* W3 = (const float*)d_in[7];
    const float* b3 = (const float*)d_in[8];
    const float* W4 = (const float*)d_in[9];
    const float* b4 = (const float*)d_in[10];
    float* out = (float*)d_out;

    k_prep<<<640, 256>>>(x, W1, b1, W2, ei);                  // launch 0
    k_agg1<<<(N_NODES * 32 + 255) / 256, 256>>>();            // launch 1
    dim3 g2(M_PAD / 64, 4);
    k_gemm2<<<g2, 128>>>();                                   // launch 2
    k_agg2_pool<<<(N_NODES * 64 + 255) / 256, 256>>>(b2, bt); // launch 3 (ncu sample)
    k_mlp<<<N_GRAPHS, 128>>>(W3, b3, W4, b4, out);            // launch 4
}